// round 14
// baseline (speedup 1.0000x reference)
#include <cuda_runtime.h>
#include <cuda_bf16.h>
#include <cuda_fp16.h>
#include <math.h>
#include <stdint.h>

#define N_NODES 50000
#define N_EDGES 600000
#define N_GRAPHS 1024
#define NB 196   // ceil(N_NODES/256)
#define PREP_BLOCKS ((N_EDGES + 255) / 256)      // 2344

// ---------------- scratch (static device globals; zero-initialized) -------------
__device__ __half d_bufAh[N_NODES * 128];   // aggregated layer output (fp16)
__device__ __half d_bufBh[N_NODES * 128];   // G = (X@W)*dinv (fp16)
__device__ float  d_dinv[N_NODES];
__device__ int    d_cnt[N_NODES];           // dst counts; self-restores to 0 in k_fill
__device__ int    d_rowptr[N_NODES + 1];
__device__ int    d_srcE[N_EDGES];
__device__ int    d_dstE[N_EDGES];
__device__ int    d_col[N_EDGES];
__device__ int    d_gptr[N_GRAPHS + 1];
__device__ unsigned short d_WhiT[3][128 * 128];  // W^T hi (fp16 bits), [n][k]
__device__ unsigned short d_WloT[3][128 * 128];  // W^T lo (fp16 bits)

__device__ __forceinline__ int clampi(int v, int hi) {
    return v < 0 ? 0 : (v > hi ? hi : v);
}

// int64-vs-int32 detection from the first 64 words of edge_index (per block).
__device__ __forceinline__ int detect_mode(const int* __restrict__ ei) {
    int z = 0;
    #pragma unroll
    for (int j = 1; j < 64; j += 2) z |= ei[j];
    return (z == 0) ? 1 : 0;
}

// ------- fused: edge prep (stage src/dst + dst histogram) | W split | gptr ------
__global__ void k_prep(const int* __restrict__ ei,
                       const float* __restrict__ W0, const float* __restrict__ W1,
                       const float* __restrict__ W2, const int* __restrict__ bat) {
    int b = blockIdx.x;
    if (b < PREP_BLOCKS) {
        __shared__ int smode;
        if (threadIdx.x == 0) smode = detect_mode(ei);
        __syncthreads();
        int mode = smode;
        int e = b * 256 + threadIdx.x;
        if (e < N_EDGES) {
            int s, d;
            if (mode) {
                s = ((const int2*)ei)[e].x;             // full-sector 64-bit loads
                d = ((const int2*)ei)[N_EDGES + e].x;
            } else {
                s = ei[e];
                d = ei[N_EDGES + e];
            }
            s = clampi(s, N_NODES - 1);
            d = clampi(d, N_NODES - 1);
            d_srcE[e] = s;
            d_dstE[e] = d;
            atomicAdd(&d_cnt[d], 1);
        }
    } else if (b < PREP_BLOCKS + 192) {
        int idx = (b - PREP_BLOCKS) * 256 + threadIdx.x;
        int which = idx >> 14, id = idx & 16383;
        const float* W = (which == 0) ? W0 : (which == 1) ? W1 : W2;
        int n = id >> 7, k = id & 127;
        float w = W[k * 128 + n];
        __half h = __float2half_rn(w);
        float r = w - __half2float(h);
        __half l = __float2half_rn(r);
        d_WhiT[which][n * 128 + k] = __half_as_ushort(h);
        d_WloT[which][n * 128 + k] = __half_as_ushort(l);
    } else {
        __shared__ int smode;
        if (threadIdx.x == 0) smode = detect_mode(ei);
        __syncthreads();
        int mode = smode;
        int g = (b - PREP_BLOCKS - 192) * 256 + threadIdx.x;
        if (g > N_GRAPHS) return;
        int lo = 0, hi = N_NODES;
        while (lo < hi) {
            int mid = (lo + hi) >> 1;
            int v = mode ? bat[2 * mid] : bat[mid];
            if (v < g) lo = mid + 1; else hi = mid;
        }
        d_gptr[g] = lo;
    }
}

// -------- fused scan: dinv + per-block offset (direct reduce) + local scan ------
__global__ void k_scan() {
    __shared__ int wred[8];
    __shared__ int s_boff;
    __shared__ int wsum[8];
    int tid = threadIdx.x, lane = tid & 31, w = tid >> 5;
    int b = blockIdx.x;

    int i = b * 256 + tid;
    int v = (i < N_NODES) ? d_cnt[i] : 0;
    if (i < N_NODES) d_dinv[i] = rsqrtf((float)v + 1.0f);

    int nwords4 = (b * 256) >> 2;
    const int4* c4 = (const int4*)d_cnt;
    int part = 0;
    for (int idx = tid; idx < nwords4; idx += 256) {
        int4 q = c4[idx];
        part += q.x + q.y + q.z + q.w;
    }
    #pragma unroll
    for (int o = 16; o; o >>= 1) part += __shfl_xor_sync(0xFFFFFFFFu, part, o);
    if (lane == 0) wred[w] = part;
    __syncthreads();
    if (tid == 0) {
        int p = 0;
        #pragma unroll
        for (int j = 0; j < 8; j++) p += wred[j];
        s_boff = p;
    }
    __syncthreads();

    int incl = v;
    #pragma unroll
    for (int o = 1; o < 32; o <<= 1) {
        int t = __shfl_up_sync(0xFFFFFFFFu, incl, o);
        if (lane >= o) incl += t;
    }
    if (lane == 31) wsum[w] = incl;
    __syncthreads();
    if (tid == 0) {
        int run = 0;
        #pragma unroll
        for (int j = 0; j < 8; j++) { int t = wsum[j]; wsum[j] = run; run += t; }
    }
    __syncthreads();
    if (i < N_NODES) d_rowptr[i] = s_boff + wsum[w] + incl - v;
    if (b == 0 && tid == 0) d_rowptr[N_NODES] = N_EDGES;
}

// CSR scatter from staged src/dst; d_cnt self-restores to 0
__global__ void k_fill() {
    int e = blockIdx.x * blockDim.x + threadIdx.x;
    if (e < N_EDGES) {
        int d = d_dstE[e];
        int pos = d_rowptr[d] + atomicSub(&d_cnt[d], 1) - 1;
        d_col[pos] = d_srcE[e];
    }
}

// ---------------- fp16 tensor-core GEMM via mma.sync + ldmatrix ----------------
// d_bufBh = fp16( (X @ W) * dinv[row] );  BM=128 x 128 tile, K=128; 2 blocks/SM
// A exact fp16; W split into fp16 hi+lo; warp tile 64x32 (mt=4, nt=4).
#define SROW 68                      // words per row (68 mod 32 = 4: conflict-free)
#define TILE_W (128 * SROW)          // 8704 words per tile
#define GEMM_SMEM (3 * TILE_W * 4)   // 104448 bytes

__device__ __forceinline__ void mma16816h(float* d, uint32_t a0, uint32_t a1,
                                          uint32_t a2, uint32_t a3,
                                          uint32_t b0, uint32_t b1) {
    asm volatile(
        "mma.sync.aligned.m16n8k16.row.col.f32.f16.f16.f32 "
        "{%0,%1,%2,%3}, {%4,%5,%6,%7}, {%8,%9}, {%0,%1,%2,%3};"
        : "+f"(d[0]), "+f"(d[1]), "+f"(d[2]), "+f"(d[3])
        : "r"(a0), "r"(a1), "r"(a2), "r"(a3), "r"(b0), "r"(b1));
}

#define LDSM_X4(r0, r1, r2, r3, addr)                                        \
    asm volatile("ldmatrix.sync.aligned.m8n8.x4.shared.b16 {%0,%1,%2,%3}, [%4];" \
        : "=r"(r0), "=r"(r1), "=r"(r2), "=r"(r3) : "r"(addr))

__device__ __forceinline__ uint32_t smem_u32(const void* p) {
    uint32_t a;
    asm("{ .reg .u64 t; cvta.to.shared.u64 t, %1; cvt.u32.u64 %0, t; }" : "=r"(a) : "l"(p));
    return a;
}

__global__ void __launch_bounds__(256, 2) k_gemm_mma(const float* __restrict__ Xext,
                                                     int useExt, int widx, int M) {
    extern __shared__ uint32_t sm[];
    uint32_t* AT = sm;                 // A fp16, exact
    uint32_t* BH = sm + TILE_W;
    uint32_t* BL = sm + 2 * TILE_W;

    int tid = threadIdx.x;
    int row0 = blockIdx.x * 128;

    // stage B (pre-split W^T fp16, coalesced u32 loads)
    const uint32_t* WH = (const uint32_t*)d_WhiT[widx];
    const uint32_t* WL = (const uint32_t*)d_WloT[widx];
    #pragma unroll
    for (int it = 0; it < 32; it++) {
        int idx = tid + it * 256;
        int n = idx >> 6, kw = idx & 63;
        BH[n * SROW + kw] = WH[idx];
        BL[n * SROW + kw] = WL[idx];
    }
    // stage A: 128 rows x 64 words of fp16
    if (useExt) {
        #pragma unroll
        for (int it = 0; it < 32; it++) {
            int idx = tid + it * 256;
            int r = idx >> 6, kw = idx & 63;
            float2 v = (row0 + r < M) ? ((const float2*)Xext)[(size_t)(row0 + r) * 64 + kw]
                                      : make_float2(0.f, 0.f);
            __half2 h2 = __floats2half2_rn(v.x, v.y);
            AT[r * SROW + kw] = *(uint32_t*)&h2;
        }
    } else {
        const uint32_t* Xh = (const uint32_t*)d_bufAh;
        #pragma unroll
        for (int it = 0; it < 32; it++) {
            int idx = tid + it * 256;
            int r = idx >> 6, kw = idx & 63;
            AT[r * SROW + kw] = (row0 + r < M) ? Xh[(size_t)(row0 + r) * 64 + kw] : 0u;
        }
    }
    __syncthreads();

    int wid = tid >> 5, lane = tid & 31;
    int g = lane >> 2, tg = lane & 3;
    int mb = (wid >> 2) * 64;                 // 2 M-groups of 64 rows
    int nb = (wid & 3) * 32;                  // 4 N-groups of 32 cols

    // ldmatrix per-lane base addresses
    int q = lane >> 3, r8 = lane & 7;
    uint32_t at_base = smem_u32(AT);
    uint32_t bh_base = smem_u32(BH);
    uint32_t bl_base = smem_u32(BL);
    uint32_t aAddr[4], bhA[2], blA[2];
    #pragma unroll
    for (int mt = 0; mt < 4; mt++) {
        int arow = mb + mt * 16 + (q & 1) * 8 + r8;
        aAddr[mt] = at_base + (uint32_t)((arow * SROW + (q >> 1) * 4) << 2);
    }
    #pragma unroll
    for (int p = 0; p < 2; p++) {
        int nrow = nb + (p * 2 + (q >> 1)) * 8 + r8;
        uint32_t off = (uint32_t)((nrow * SROW + (q & 1) * 4) << 2);
        bhA[p] = bh_base + off;
        blA[p] = bl_base + off;
    }

    float acc[4][4][4];
    #pragma unroll
    for (int mt = 0; mt < 4; mt++)
        #pragma unroll
        for (int nt = 0; nt < 4; nt++)
            #pragma unroll
            for (int qq = 0; qq < 4; qq++) acc[mt][nt][qq] = 0.f;

    #pragma unroll
    for (int ks = 0; ks < 8; ks++) {
        uint32_t koff = ks * 32;              // 8 words = 32 bytes per k-step
        uint32_t a[4][4];
        #pragma unroll
        for (int mt = 0; mt < 4; mt++)
            LDSM_X4(a[mt][0], a[mt][1], a[mt][2], a[mt][3], aAddr[mt] + koff);
        #pragma unroll
        for (int p = 0; p < 2; p++) {
            uint32_t bh[4], bl[4];
            LDSM_X4(bh[0], bh[1], bh[2], bh[3], bhA[p] + koff);
            LDSM_X4(bl[0], bl[1], bl[2], bl[3], blA[p] + koff);
            #pragma unroll
            for (int h = 0; h < 2; h++) {
                int nt = 2 * p + h;
                #pragma unroll
                for (int mt = 0; mt < 4; mt++) {
                    mma16816h(acc[mt][nt], a[mt][0], a[mt][1], a[mt][2], a[mt][3],
                              bh[h * 2], bh[h * 2 + 1]);
                    mma16816h(acc[mt][nt], a[mt][0], a[mt][1], a[mt][2], a[mt][3],
                              bl[h * 2], bl[h * 2 + 1]);
                }
            }
        }
    }

    // epilogue: scale by dinv[row], store fp16
    uint32_t* Gout = (uint32_t*)d_bufBh;
    #pragma unroll
    for (int mt = 0; mt < 4; mt++) {
        int r0 = row0 + mb + mt * 16 + g;
        int r1 = r0 + 8;
        float dv0 = (r0 < M) ? d_dinv[r0] : 0.f;
        float dv1 = (r1 < M) ? d_dinv[r1] : 0.f;
        #pragma unroll
        for (int nt = 0; nt < 4; nt++) {
            int c = nb + nt * 8 + tg * 2;
            if (r0 < M) {
                __half2 p = __floats2half2_rn(acc[mt][nt][0] * dv0, acc[mt][nt][1] * dv0);
                Gout[(size_t)r0 * 64 + (c >> 1)] = *(uint32_t*)&p;
            }
            if (r1 < M) {
                __half2 p = __floats2half2_rn(acc[mt][nt][2] * dv1, acc[mt][nt][3] * dv1);
                Gout[(size_t)r1 * 64 + (c >> 1)] = *(uint32_t*)&p;
            }
        }
    }
}

// ---------------- aggregate: outh = fp16(relu(dinv[i]*(G[i]+sum G[src]) + b)) ---
__device__ __forceinline__ float4 h4f(uint2 u) {
    float2 a = __half22float2(*(__half2*)&u.x);
    float2 b = __half22float2(*(__half2*)&u.y);
    return make_float4(a.x, a.y, b.x, b.y);
}

__global__ void k_agg(const float* __restrict__ bias) {
    int warp = (blockIdx.x * blockDim.x + threadIdx.x) >> 5;
    int lane = threadIdx.x & 31;
    if (warp >= N_NODES) return;
    const uint2* __restrict__ G = (const uint2*)d_bufBh;

    float4 acc = h4f(G[(size_t)warp * 32 + lane]);        // self loop
    int s = d_rowptr[warp], e = d_rowptr[warp + 1];
    int j = s;
    for (; j + 1 < e; j += 2) {
        int s0 = d_col[j], s1 = d_col[j + 1];
        float4 v0 = h4f(G[(size_t)s0 * 32 + lane]);
        float4 v1 = h4f(G[(size_t)s1 * 32 + lane]);
        acc.x += v0.x + v1.x; acc.y += v0.y + v1.y;
        acc.z += v0.z + v1.z; acc.w += v0.w + v1.w;
    }
    if (j < e) {
        float4 v0 = h4f(G[(size_t)d_col[j] * 32 + lane]);
        acc.x += v0.x; acc.y += v0.y; acc.z += v0.z; acc.w += v0.w;
    }
    float dv = d_dinv[warp];
    float4 b = ((const float4*)bias)[lane];
    float ox = fmaxf(fmaf(acc.x, dv, b.x), 0.f);
    float oy = fmaxf(fmaf(acc.y, dv, b.y), 0.f);
    float oz = fmaxf(fmaf(acc.z, dv, b.z), 0.f);
    float ow = fmaxf(fmaf(acc.w, dv, b.w), 0.f);
    __half2 p0 = __floats2half2_rn(ox, oy);
    __half2 p1 = __floats2half2_rn(oz, ow);
    uint2 w;
    w.x = *(uint32_t*)&p0;
    w.y = *(uint32_t*)&p1;
    ((uint2*)d_bufAh)[(size_t)warp * 32 + lane] = w;
}

// ---------------- fused head: pool + mlp1 + mlp2 + out ----------------
__global__ void k_head(const float* __restrict__ Wl1, const float* __restrict__ bl1,
                       const float* __restrict__ Wl2, const float* __restrict__ bl2,
                       const float* __restrict__ Wl3, const float* __restrict__ bl3,
                       float* __restrict__ out) {
    __shared__ float a[256];
    __shared__ float o1[128];
    __shared__ float o2[128];
    __shared__ float red[4];
    int g = blockIdx.x, t = threadIdx.x;
    int lane = t & 31, w = t >> 5;

    int s = d_gptr[g], e = d_gptr[g + 1];
    float mx = 0.f, sm = 0.f;
    for (int n = s; n < e; n++) {
        float v = __half2float(d_bufAh[(size_t)n * 128 + t]);
        mx = fmaxf(mx, v);
        sm += v;
    }
    a[t] = mx;
    a[t + 128] = sm / fmaxf((float)(e - s), 1.f);
    __syncthreads();

    float acc = bl1[t];
    #pragma unroll 8
    for (int k = 0; k < 256; k++) acc = fmaf(a[k], Wl1[k * 128 + t], acc);
    o1[t] = fmaxf(acc, 0.f);
    __syncthreads();

    acc = bl2[t];
    #pragma unroll 8
    for (int k = 0; k < 128; k++) acc = fmaf(o1[k], Wl2[k * 128 + t], acc);
    o2[t] = fmaxf(acc, 0.f);
    __syncthreads();

    float p = o2[t] * Wl3[t];
    #pragma unroll
    for (int o = 16; o; o >>= 1) p += __shfl_xor_sync(0xFFFFFFFFu, p, o);
    if (lane == 0) red[w] = p;
    __syncthreads();
    if (t == 0) {
        float z = red[0] + red[1] + red[2] + red[3] + bl3[0];
        out[g] = 1.f / (1.f + expf(-z));
    }
}

// ---------------- launch ----------------
extern "C" void kernel_launch(void* const* d_in, const int* in_sizes, int n_in,
                              void* d_out, int out_size) {
    const float* x   = (const float*)d_in[0];
    const int*   ei  = (const int*)d_in[1];
    const int*   bat = (const int*)d_in[2];
    const float* W0 = (const float*)d_in[3],  *b0 = (const float*)d_in[4];
    const float* W1 = (const float*)d_in[5],  *b1 = (const float*)d_in[6];
    const float* W2 = (const float*)d_in[7],  *b2 = (const float*)d_in[8];
    const float* Wl1 = (const float*)d_in[9],  *bl1 = (const float*)d_in[10];
    const float* Wl2 = (const float*)d_in[11], *bl2 = (const float*)d_in[12];
    const float* Wl3 = (const float*)d_in[13], *bl3 = (const float*)d_in[14];
    float* out = (float*)d_out;

    static int inited = 0;
    if (!inited) {
        cudaFuncSetAttribute(k_gemm_mma, cudaFuncAttributeMaxDynamicSharedMemorySize,
                             GEMM_SMEM);
        inited = 1;
    }

    const int gemm_blocks = (N_NODES + 127) / 128;    // 391
    const int agg_blocks  = (N_NODES * 32 + 255) / 256;

    // graph structure (d_cnt starts 0; self-restores in k_fill)
    k_prep<<<PREP_BLOCKS + 192 + 5, 256>>>(ei, W0, W1, W2, bat);
    k_scan<<<NB, 256>>>();
    k_fill<<<(N_EDGES + 255) / 256, 256>>>();

    k_gemm_mma<<<gemm_blocks, 256, GEMM_SMEM>>>(x, 1, 0, N_NODES);
    k_agg<<<agg_blocks, 256>>>(b0);

    k_gemm_mma<<<gemm_blocks, 256, GEMM_SMEM>>>(x, 0, 1, N_NODES);
    k_agg<<<agg_blocks, 256>>>(b1);

    k_gemm_mma<<<gemm_blocks, 256, GEMM_SMEM>>>(x, 0, 2, N_NODES);
    k_agg<<<agg_blocks, 256>>>(b2);

    k_head<<<N_GRAPHS, 128>>>(Wl1, bl1, Wl2, bl2, Wl3, bl3, out);
}

// round 15
// speedup vs baseline: 1.1483x; 1.1483x over previous
#include <cuda_runtime.h>
#include <cuda_bf16.h>
#include <cuda_fp16.h>
#include <math.h>
#include <stdint.h>

#define N_NODES 50000
#define N_EDGES 600000
#define N_GRAPHS 1024
#define NB 196   // ceil(N_NODES/256)
#define PREP_BLOCKS ((N_EDGES + 255) / 256)      // 2344

// ---------------- scratch (static device globals; zero-initialized) -------------
__device__ __half d_bufAh[N_NODES * 128];   // aggregated layer output (fp16)
__device__ __half d_bufBh[N_NODES * 128];   // G = (X@W)*dinv (fp16)
__device__ float  d_dinv[N_NODES];
__device__ int    d_cnt[N_NODES];           // dst counts; self-restores to 0 in k_fill
__device__ int    d_rowptr[N_NODES + 1];
__device__ int    d_srcE[N_EDGES];
__device__ int    d_dstE[N_EDGES];
__device__ int    d_col[N_EDGES];
__device__ int    d_gptr[N_GRAPHS + 1];
__device__ unsigned short d_WhT[3][128 * 128];   // W^T (fp16 bits), [n][k]

__device__ __forceinline__ int clampi(int v, int hi) {
    return v < 0 ? 0 : (v > hi ? hi : v);
}

// int64-vs-int32 detection from the first 64 words of edge_index (per block).
__device__ __forceinline__ int detect_mode(const int* __restrict__ ei) {
    int z = 0;
    #pragma unroll
    for (int j = 1; j < 64; j += 2) z |= ei[j];
    return (z == 0) ? 1 : 0;
}

// ------- fused: edge prep (stage src/dst + dst histogram) | W convert | gptr ----
__global__ void k_prep(const int* __restrict__ ei,
                       const float* __restrict__ W0, const float* __restrict__ W1,
                       const float* __restrict__ W2, const int* __restrict__ bat) {
    int b = blockIdx.x;
    if (b < PREP_BLOCKS) {
        __shared__ int smode;
        if (threadIdx.x == 0) smode = detect_mode(ei);
        __syncthreads();
        int mode = smode;
        int e = b * 256 + threadIdx.x;
        if (e < N_EDGES) {
            int s, d;
            if (mode) {
                s = ((const int2*)ei)[e].x;             // full-sector 64-bit loads
                d = ((const int2*)ei)[N_EDGES + e].x;
            } else {
                s = ei[e];
                d = ei[N_EDGES + e];
            }
            s = clampi(s, N_NODES - 1);
            d = clampi(d, N_NODES - 1);
            d_srcE[e] = s;
            d_dstE[e] = d;
            atomicAdd(&d_cnt[d], 1);
        }
    } else if (b < PREP_BLOCKS + 192) {
        int idx = (b - PREP_BLOCKS) * 256 + threadIdx.x;
        int which = idx >> 14, id = idx & 16383;
        const float* W = (which == 0) ? W0 : (which == 1) ? W1 : W2;
        int n = id >> 7, k = id & 127;
        d_WhT[which][n * 128 + k] = __half_as_ushort(__float2half_rn(W[k * 128 + n]));
    } else {
        __shared__ int smode;
        if (threadIdx.x == 0) smode = detect_mode(ei);
        __syncthreads();
        int mode = smode;
        int g = (b - PREP_BLOCKS - 192) * 256 + threadIdx.x;
        if (g > N_GRAPHS) return;
        int lo = 0, hi = N_NODES;
        while (lo < hi) {
            int mid = (lo + hi) >> 1;
            int v = mode ? bat[2 * mid] : bat[mid];
            if (v < g) lo = mid + 1; else hi = mid;
        }
        d_gptr[g] = lo;
    }
}

// -------- fused scan: dinv + per-block offset (direct reduce) + local scan ------
__global__ void k_scan() {
    __shared__ int wred[8];
    __shared__ int s_boff;
    __shared__ int wsum[8];
    int tid = threadIdx.x, lane = tid & 31, w = tid >> 5;
    int b = blockIdx.x;

    int i = b * 256 + tid;
    int v = (i < N_NODES) ? d_cnt[i] : 0;
    if (i < N_NODES) d_dinv[i] = rsqrtf((float)v + 1.0f);

    int nwords4 = (b * 256) >> 2;
    const int4* c4 = (const int4*)d_cnt;
    int part = 0;
    for (int idx = tid; idx < nwords4; idx += 256) {
        int4 q = c4[idx];
        part += q.x + q.y + q.z + q.w;
    }
    #pragma unroll
    for (int o = 16; o; o >>= 1) part += __shfl_xor_sync(0xFFFFFFFFu, part, o);
    if (lane == 0) wred[w] = part;
    __syncthreads();
    if (tid == 0) {
        int p = 0;
        #pragma unroll
        for (int j = 0; j < 8; j++) p += wred[j];
        s_boff = p;
    }
    __syncthreads();

    int incl = v;
    #pragma unroll
    for (int o = 1; o < 32; o <<= 1) {
        int t = __shfl_up_sync(0xFFFFFFFFu, incl, o);
        if (lane >= o) incl += t;
    }
    if (lane == 31) wsum[w] = incl;
    __syncthreads();
    if (tid == 0) {
        int run = 0;
        #pragma unroll
        for (int j = 0; j < 8; j++) { int t = wsum[j]; wsum[j] = run; run += t; }
    }
    __syncthreads();
    if (i < N_NODES) d_rowptr[i] = s_boff + wsum[w] + incl - v;
    if (b == 0 && tid == 0) d_rowptr[N_NODES] = N_EDGES;
}

// CSR scatter from staged src/dst; d_cnt self-restores to 0
__global__ void k_fill() {
    int e = blockIdx.x * blockDim.x + threadIdx.x;
    if (e < N_EDGES) {
        int d = d_dstE[e];
        int pos = d_rowptr[d] + atomicSub(&d_cnt[d], 1) - 1;
        d_col[pos] = d_srcE[e];
    }
}

// ---------------- fp16 tensor-core GEMM via mma.sync ----------------
// d_bufBh = fp16( (X @ W) * dinv[row] );  BM=128 x 128 tile, K=128; 2 blocks/SM
// A exact fp16 (1 tile); W plain fp16 (1 tile); 1 mma term. R12 geometry.
#define SROW 68                      // words per row (68 mod 32 = 4: conflict-free)
#define TILE_W (128 * SROW)          // 8704 words per tile
#define GEMM_SMEM (2 * TILE_W * 4)   // 69632 bytes

__device__ __forceinline__ void mma16816h(float* d, uint32_t a0, uint32_t a1,
                                          uint32_t a2, uint32_t a3,
                                          uint32_t b0, uint32_t b1) {
    asm volatile(
        "mma.sync.aligned.m16n8k16.row.col.f32.f16.f16.f32 "
        "{%0,%1,%2,%3}, {%4,%5,%6,%7}, {%8,%9}, {%0,%1,%2,%3};"
        : "+f"(d[0]), "+f"(d[1]), "+f"(d[2]), "+f"(d[3])
        : "r"(a0), "r"(a1), "r"(a2), "r"(a3), "r"(b0), "r"(b1));
}

__global__ void __launch_bounds__(256, 2) k_gemm_mma(const float* __restrict__ Xext,
                                                     int useExt, int widx, int M) {
    extern __shared__ uint32_t sm[];
    uint32_t* AT = sm;                 // A fp16, exact
    uint32_t* BT = sm + TILE_W;        // W^T fp16

    int tid = threadIdx.x;
    int row0 = blockIdx.x * 128;

    // stage B (W^T fp16, coalesced u32 loads)
    const uint32_t* WH = (const uint32_t*)d_WhT[widx];
    #pragma unroll
    for (int it = 0; it < 32; it++) {
        int idx = tid + it * 256;
        int n = idx >> 6, kw = idx & 63;
        BT[n * SROW + kw] = WH[idx];
    }
    // stage A: 128 rows x 64 words of fp16
    if (useExt) {
        #pragma unroll
        for (int it = 0; it < 32; it++) {
            int idx = tid + it * 256;
            int r = idx >> 6, kw = idx & 63;
            float2 v = (row0 + r < M) ? ((const float2*)Xext)[(size_t)(row0 + r) * 64 + kw]
                                      : make_float2(0.f, 0.f);
            __half2 h2 = __floats2half2_rn(v.x, v.y);
            AT[r * SROW + kw] = *(uint32_t*)&h2;
        }
    } else {
        const uint32_t* Xh = (const uint32_t*)d_bufAh;
        #pragma unroll
        for (int it = 0; it < 32; it++) {
            int idx = tid + it * 256;
            int r = idx >> 6, kw = idx & 63;
            AT[r * SROW + kw] = (row0 + r < M) ? Xh[(size_t)(row0 + r) * 64 + kw] : 0u;
        }
    }
    __syncthreads();

    int wid = tid >> 5, lane = tid & 31;
    int g = lane >> 2, tg = lane & 3;
    int mb = (wid >> 1) * 32;                 // 4 M-groups of 32 rows
    int nb = (wid & 1) * 64;                  // 2 N-groups of 64 cols

    float acc[2][8][4];
    #pragma unroll
    for (int mt = 0; mt < 2; mt++)
        #pragma unroll
        for (int nt = 0; nt < 8; nt++)
            #pragma unroll
            for (int q = 0; q < 4; q++) acc[mt][nt][q] = 0.f;

    #pragma unroll
    for (int ks = 0; ks < 8; ks++) {
        int kw = ks * 8;
        uint32_t a[2][4];
        #pragma unroll
        for (int mt = 0; mt < 2; mt++) {
            int r0 = (mb + mt * 16 + g) * SROW, r1 = (mb + mt * 16 + 8 + g) * SROW;
            a[mt][0] = AT[r0 + kw + tg];     a[mt][1] = AT[r1 + kw + tg];
            a[mt][2] = AT[r0 + kw + 4 + tg]; a[mt][3] = AT[r1 + kw + 4 + tg];
        }
        #pragma unroll
        for (int nt = 0; nt < 8; nt++) {
            int nr = (nb + nt * 8 + g) * SROW;
            uint32_t b0 = BT[nr + kw + tg], b1 = BT[nr + kw + 4 + tg];
            #pragma unroll
            for (int mt = 0; mt < 2; mt++)
                mma16816h(acc[mt][nt], a[mt][0], a[mt][1], a[mt][2], a[mt][3], b0, b1);
        }
    }

    // epilogue: scale by dinv[row], store fp16
    uint32_t* Gout = (uint32_t*)d_bufBh;
    #pragma unroll
    for (int mt = 0; mt < 2; mt++) {
        int r0 = row0 + mb + mt * 16 + g;
        int r1 = r0 + 8;
        float dv0 = (r0 < M) ? d_dinv[r0] : 0.f;
        float dv1 = (r1 < M) ? d_dinv[r1] : 0.f;
        #pragma unroll
        for (int nt = 0; nt < 8; nt++) {
            int c = nb + nt * 8 + tg * 2;
            if (r0 < M) {
                __half2 p = __floats2half2_rn(acc[mt][nt][0] * dv0, acc[mt][nt][1] * dv0);
                Gout[(size_t)r0 * 64 + (c >> 1)] = *(uint32_t*)&p;
            }
            if (r1 < M) {
                __half2 p = __floats2half2_rn(acc[mt][nt][2] * dv1, acc[mt][nt][3] * dv1);
                Gout[(size_t)r1 * 64 + (c >> 1)] = *(uint32_t*)&p;
            }
        }
    }
}

// ---------------- aggregate: outh = fp16(relu(dinv[i]*(G[i]+sum G[src]) + b)) ---
__device__ __forceinline__ float4 h4f(uint2 u) {
    float2 a = __half22float2(*(__half2*)&u.x);
    float2 b = __half22float2(*(__half2*)&u.y);
    return make_float4(a.x, a.y, b.x, b.y);
}

__global__ void k_agg(const float* __restrict__ bias) {
    int warp = (blockIdx.x * blockDim.x + threadIdx.x) >> 5;
    int lane = threadIdx.x & 31;
    if (warp >= N_NODES) return;
    const uint2* __restrict__ G = (const uint2*)d_bufBh;

    float4 acc = h4f(G[(size_t)warp * 32 + lane]);        // self loop
    int s = d_rowptr[warp], e = d_rowptr[warp + 1];
    int j = s;
    for (; j + 1 < e; j += 2) {
        int s0 = d_col[j], s1 = d_col[j + 1];
        float4 v0 = h4f(G[(size_t)s0 * 32 + lane]);
        float4 v1 = h4f(G[(size_t)s1 * 32 + lane]);
        acc.x += v0.x + v1.x; acc.y += v0.y + v1.y;
        acc.z += v0.z + v1.z; acc.w += v0.w + v1.w;
    }
    if (j < e) {
        float4 v0 = h4f(G[(size_t)d_col[j] * 32 + lane]);
        acc.x += v0.x; acc.y += v0.y; acc.z += v0.z; acc.w += v0.w;
    }
    float dv = d_dinv[warp];
    float4 b = ((const float4*)bias)[lane];
    float ox = fmaxf(fmaf(acc.x, dv, b.x), 0.f);
    float oy = fmaxf(fmaf(acc.y, dv, b.y), 0.f);
    float oz = fmaxf(fmaf(acc.z, dv, b.z), 0.f);
    float ow = fmaxf(fmaf(acc.w, dv, b.w), 0.f);
    __half2 p0 = __floats2half2_rn(ox, oy);
    __half2 p1 = __floats2half2_rn(oz, ow);
    uint2 w;
    w.x = *(uint32_t*)&p0;
    w.y = *(uint32_t*)&p1;
    ((uint2*)d_bufAh)[(size_t)warp * 32 + lane] = w;
}

// ---------------- fused head: pool + mlp1 + mlp2 + out ----------------
__global__ void k_head(const float* __restrict__ Wl1, const float* __restrict__ bl1,
                       const float* __restrict__ Wl2, const float* __restrict__ bl2,
                       const float* __restrict__ Wl3, const float* __restrict__ bl3,
                       float* __restrict__ out) {
    __shared__ float a[256];
    __shared__ float o1[128];
    __shared__ float o2[128];
    __shared__ float red[4];
    int g = blockIdx.x, t = threadIdx.x;
    int lane = t & 31, w = t >> 5;

    int s = d_gptr[g], e = d_gptr[g + 1];
    float mx = 0.f, sm = 0.f;
    for (int n = s; n < e; n++) {
        float v = __half2float(d_bufAh[(size_t)n * 128 + t]);
        mx = fmaxf(mx, v);
        sm += v;
    }
    a[t] = mx;
    a[t + 128] = sm / fmaxf((float)(e - s), 1.f);
    __syncthreads();

    float acc = bl1[t];
    #pragma unroll 8
    for (int k = 0; k < 256; k++) acc = fmaf(a[k], Wl1[k * 128 + t], acc);
    o1[t] = fmaxf(acc, 0.f);
    __syncthreads();

    acc = bl2[t];
    #pragma unroll 8
    for (int k = 0; k < 128; k++) acc = fmaf(o1[k], Wl2[k * 128 + t], acc);
    o2[t] = fmaxf(acc, 0.f);
    __syncthreads();

    float p = o2[t] * Wl3[t];
    #pragma unroll
    for (int o = 16; o; o >>= 1) p += __shfl_xor_sync(0xFFFFFFFFu, p, o);
    if (lane == 0) red[w] = p;
    __syncthreads();
    if (t == 0) {
        float z = red[0] + red[1] + red[2] + red[3] + bl3[0];
        out[g] = 1.f / (1.f + expf(-z));
    }
}

// ---------------- launch ----------------
extern "C" void kernel_launch(void* const* d_in, const int* in_sizes, int n_in,
                              void* d_out, int out_size) {
    const float* x   = (const float*)d_in[0];
    const int*   ei  = (const int*)d_in[1];
    const int*   bat = (const int*)d_in[2];
    const float* W0 = (const float*)d_in[3],  *b0 = (const float*)d_in[4];
    const float* W1 = (const float*)d_in[5],  *b1 = (const float*)d_in[6];
    const float* W2 = (const float*)d_in[7],  *b2 = (const float*)d_in[8];
    const float* Wl1 = (const float*)d_in[9],  *bl1 = (const float*)d_in[10];
    const float* Wl2 = (const float*)d_in[11], *bl2 = (const float*)d_in[12];
    const float* Wl3 = (const float*)d_in[13], *bl3 = (const float*)d_in[14];
    float* out = (float*)d_out;

    static int inited = 0;
    if (!inited) {
        cudaFuncSetAttribute(k_gemm_mma, cudaFuncAttributeMaxDynamicSharedMemorySize,
                             GEMM_SMEM);
        inited = 1;
    }

    const int gemm_blocks = (N_NODES + 127) / 128;    // 391
    const int agg_blocks  = (N_NODES * 32 + 255) / 256;

    // graph structure (d_cnt starts 0; self-restores in k_fill)
    k_prep<<<PREP_BLOCKS + 192 + 5, 256>>>(ei, W0, W1, W2, bat);
    k_scan<<<NB, 256>>>();
    k_fill<<<(N_EDGES + 255) / 256, 256>>>();

    k_gemm_mma<<<gemm_blocks, 256, GEMM_SMEM>>>(x, 1, 0, N_NODES);
    k_agg<<<agg_blocks, 256>>>(b0);

    k_gemm_mma<<<gemm_blocks, 256, GEMM_SMEM>>>(x, 0, 1, N_NODES);
    k_agg<<<agg_blocks, 256>>>(b1);

    k_gemm_mma<<<gemm_blocks, 256, GEMM_SMEM>>>(x, 0, 2, N_NODES);
    k_agg<<<agg_blocks, 256>>>(b2);

    k_head<<<N_GRAPHS, 128>>>(Wl1, bl1, Wl2, bl2, Wl3, bl3, out);
}